// round 2
// baseline (speedup 1.0000x reference)
#include <cuda_runtime.h>
#include <math_constants.h>

// Problem constants
#define B_ 32
#define L_ 8192
#define C_ 256
#define S_ 8                  // L-splits (CHUNK = 1024)
#define CHUNK_ (L_ / S_)
#define MLP_ 16

// Partials, plane-major: part[k][(b*S+s)*C + c], k in 0..5
// plane stride P = B*S*C = 65536 floats; total 1.5 MB.
#define PLANE_ (B_ * S_ * C_)
__device__ float g_part[6 * PLANE_];

__device__ __forceinline__ void track(float v,
                                      float& mx0, float& mx1, float& mx2,
                                      float& mn0, float& mn1, float& mn2) {
    if (v > mx2) {
        if (v > mx0)      { mx2 = mx1; mx1 = mx0; mx0 = v; }
        else if (v > mx1) { mx2 = mx1; mx1 = v; }
        else              { mx2 = v; }
    }
    if (v < mn2) {
        if (v < mn0)      { mn2 = mn1; mn1 = mn0; mn0 = v; }
        else if (v < mn1) { mn2 = mn1; mn1 = v; }
        else              { mn2 = v; }
    }
}

// Pass 1: grid (S, B) = 256 blocks x 256 threads => 65k threads, single
// resident wave. Thread c scans CHUNK_ l-values, 16 loads in flight.
__global__ __launch_bounds__(C_) void kmm_partial(const float* __restrict__ x) {
    const int c = threadIdx.x;
    const int s = blockIdx.x;
    const int b = blockIdx.y;

    const float* __restrict__ p =
        x + ((size_t)b * L_ + (size_t)s * CHUNK_) * C_ + c;

    float mx0 = -CUDART_INF_F, mx1 = -CUDART_INF_F, mx2 = -CUDART_INF_F;
    float mn0 =  CUDART_INF_F, mn1 =  CUDART_INF_F, mn2 =  CUDART_INF_F;

    for (int l = 0; l < CHUNK_; l += MLP_) {
        float v[MLP_];
#pragma unroll
        for (int j = 0; j < MLP_; j++)
            v[j] = __ldg(p + (size_t)(l + j) * C_);
#pragma unroll
        for (int j = 0; j < MLP_; j++)
            track(v[j], mx0, mx1, mx2, mn0, mn1, mn2);
    }

    const int row = (b * S_ + s) * C_ + c;
    g_part[0 * PLANE_ + row] = mn0;
    g_part[1 * PLANE_ + row] = mn1;
    g_part[2 * PLANE_ + row] = mn2;
    g_part[3 * PLANE_ + row] = mx0;
    g_part[4 * PLANE_ + row] = mx1;
    g_part[5 * PLANE_ + row] = mx2;
}

// Pass 2: one thread per (b,c) row, 8192 threads. Consecutive threads read
// consecutive c => fully coalesced plane loads. Merges S_=8 sorted triples.
__global__ __launch_bounds__(256) void kmm_reduce(float* __restrict__ out) {
    const int idx = blockIdx.x * blockDim.x + threadIdx.x;  // b*C + c
    if (idx >= B_ * C_) return;
    const int b = idx / C_;
    const int c = idx % C_;

    float mx0 = -CUDART_INF_F, mx1 = -CUDART_INF_F, mx2 = -CUDART_INF_F;
    float mn0 =  CUDART_INF_F, mn1 =  CUDART_INF_F, mn2 =  CUDART_INF_F;

#pragma unroll
    for (int s = 0; s < S_; s++) {
        const int row = (b * S_ + s) * C_ + c;
        float p0 = g_part[0 * PLANE_ + row];
        float p1 = g_part[1 * PLANE_ + row];
        float p2 = g_part[2 * PLANE_ + row];
        float q0 = g_part[3 * PLANE_ + row];
        float q1 = g_part[4 * PLANE_ + row];
        float q2 = g_part[5 * PLANE_ + row];

        if (p0 < mn2) {
            if (p0 < mn0)      { mn2 = mn1; mn1 = mn0; mn0 = p0; }
            else if (p0 < mn1) { mn2 = mn1; mn1 = p0; }
            else               { mn2 = p0; }
        }
        if (p1 < mn2) {
            if (p1 < mn0)      { mn2 = mn1; mn1 = mn0; mn0 = p1; }
            else if (p1 < mn1) { mn2 = mn1; mn1 = p1; }
            else               { mn2 = p1; }
        }
        if (p2 < mn2) {
            if (p2 < mn0)      { mn2 = mn1; mn1 = mn0; mn0 = p2; }
            else if (p2 < mn1) { mn2 = mn1; mn1 = p2; }
            else               { mn2 = p2; }
        }
        if (q0 > mx2) {
            if (q0 > mx0)      { mx2 = mx1; mx1 = mx0; mx0 = q0; }
            else if (q0 > mx1) { mx2 = mx1; mx1 = q0; }
            else               { mx2 = q0; }
        }
        if (q1 > mx2) {
            if (q1 > mx0)      { mx2 = mx1; mx1 = mx0; mx0 = q1; }
            else if (q1 > mx1) { mx2 = mx1; mx1 = q1; }
            else               { mx2 = q1; }
        }
        if (q2 > mx2) {
            if (q2 > mx0)      { mx2 = mx1; mx1 = mx0; mx0 = q2; }
            else if (q2 > mx1) { mx2 = mx1; mx1 = q2; }
            else               { mx2 = q2; }
        }
    }

    float* r = out + (size_t)idx * 6;
    r[0] = mn0; r[1] = mn1; r[2] = mn2;
    r[3] = mx0; r[4] = mx1; r[5] = mx2;
}

extern "C" void kernel_launch(void* const* d_in, const int* in_sizes, int n_in,
                              void* d_out, int out_size) {
    const float* x = (const float*)d_in[0];
    float* out = (float*)d_out;

    dim3 grid1(S_, B_);
    kmm_partial<<<grid1, C_>>>(x);

    const int total = B_ * C_;
    kmm_reduce<<<(total + 255) / 256, 256>>>(out);
}

// round 3
// speedup vs baseline: 1.1421x; 1.1421x over previous
#include <cuda_runtime.h>
#include <math_constants.h>

// Problem constants
#define B_ 32
#define L_ 8192
#define C_ 256
#define S_ 32                 // L-splits (CHUNK = 256)
#define CHUNK_ (L_ / S_)
#define MLP_ 8

// Partials, plane-major: part[k][(b*S+s)*C + c], k in 0..5. 6 MB total.
#define PLANE_ (B_ * S_ * C_)
__device__ float g_part[6 * PLANE_];

__device__ __forceinline__ void ins_min(float v, float& mn0, float& mn1, float& mn2) {
    if (v < mn2) {
        if (v < mn1) {
            mn2 = mn1;
            if (v < mn0) { mn1 = mn0; mn0 = v; }
            else         { mn1 = v; }
        } else {
            mn2 = v;
        }
    }
}

__device__ __forceinline__ void ins_max(float v, float& mx0, float& mx1, float& mx2) {
    if (v > mx2) {
        if (v > mx1) {
            mx2 = mx1;
            if (v > mx0) { mx1 = mx0; mx0 = v; }
            else         { mx1 = v; }
        } else {
            mx2 = v;
        }
    }
}

// Pass 1: grid (S, B) = 1024 blocks x 256 threads = one full resident wave
// at 8 blocks/SM. Thread c scans CHUNK_ l-values with a pair min/max
// prefilter; warp loads are 128B-coalesced along c.
__global__ __launch_bounds__(C_, 8) void kmm_partial(const float* __restrict__ x) {
    const int c = threadIdx.x;
    const int s = blockIdx.x;
    const int b = blockIdx.y;

    const float* __restrict__ p =
        x + ((size_t)b * L_ + (size_t)s * CHUNK_) * C_ + c;

    float mx0 = -CUDART_INF_F, mx1 = -CUDART_INF_F, mx2 = -CUDART_INF_F;
    float mn0 =  CUDART_INF_F, mn1 =  CUDART_INF_F, mn2 =  CUDART_INF_F;

    for (int l = 0; l < CHUNK_; l += MLP_) {
        float v[MLP_];
#pragma unroll
        for (int j = 0; j < MLP_; j++)
            v[j] = __ldg(p + (size_t)(l + j) * C_);
#pragma unroll
        for (int j = 0; j < MLP_; j += 2) {
            float lo = fminf(v[j], v[j + 1]);
            float hi = fmaxf(v[j], v[j + 1]);
            if (lo < mn2) {
                ins_min(v[j],     mn0, mn1, mn2);
                ins_min(v[j + 1], mn0, mn1, mn2);
            }
            if (hi > mx2) {
                ins_max(v[j],     mx0, mx1, mx2);
                ins_max(v[j + 1], mx0, mx1, mx2);
            }
        }
    }

    const int row = (b * S_ + s) * C_ + c;
    g_part[0 * PLANE_ + row] = mn0;
    g_part[1 * PLANE_ + row] = mn1;
    g_part[2 * PLANE_ + row] = mn2;
    g_part[3 * PLANE_ + row] = mx0;
    g_part[4 * PLANE_ + row] = mx1;
    g_part[5 * PLANE_ + row] = mx2;
}

// Pass 2: one thread per (b,c) row. 128 blocks x 64 threads -> spreads over
// ~128 SMs (round-2 version used 32 blocks and was latency-bound).
// Plane-major loads are coalesced (lane stride = 4B).
__global__ __launch_bounds__(64) void kmm_reduce(float* __restrict__ out) {
    const int idx = blockIdx.x * 64 + threadIdx.x;  // b*C + c
    const int b = idx >> 8;
    const int c = idx & 255;

    float mx0 = -CUDART_INF_F, mx1 = -CUDART_INF_F, mx2 = -CUDART_INF_F;
    float mn0 =  CUDART_INF_F, mn1 =  CUDART_INF_F, mn2 =  CUDART_INF_F;

#pragma unroll 4
    for (int s = 0; s < S_; s++) {
        const int row = (b * S_ + s) * C_ + c;
        float p0 = g_part[0 * PLANE_ + row];
        float p1 = g_part[1 * PLANE_ + row];
        float p2 = g_part[2 * PLANE_ + row];
        float q0 = g_part[3 * PLANE_ + row];
        float q1 = g_part[4 * PLANE_ + row];
        float q2 = g_part[5 * PLANE_ + row];

        if (p0 < mn2) {
            ins_min(p0, mn0, mn1, mn2);
            ins_min(p1, mn0, mn1, mn2);
            ins_min(p2, mn0, mn1, mn2);
        }
        if (q0 > mx2) {
            ins_max(q0, mx0, mx1, mx2);
            ins_max(q1, mx0, mx1, mx2);
            ins_max(q2, mx0, mx1, mx2);
        }
    }

    float* r = out + (size_t)idx * 6;
    r[0] = mn0; r[1] = mn1; r[2] = mn2;
    r[3] = mx0; r[4] = mx1; r[5] = mx2;
}

extern "C" void kernel_launch(void* const* d_in, const int* in_sizes, int n_in,
                              void* d_out, int out_size) {
    const float* x = (const float*)d_in[0];
    float* out = (float*)d_out;

    dim3 grid1(S_, B_);
    kmm_partial<<<grid1, C_>>>(x);

    kmm_reduce<<<(B_ * C_) / 64, 64>>>(out);
}

// round 4
// speedup vs baseline: 1.4468x; 1.2668x over previous
#include <cuda_runtime.h>
#include <math_constants.h>

// Problem constants
#define B_ 32
#define L_ 8192
#define C_ 256
#define S_ 32                 // L-splits == warp size (reduce: lane = s)
#define CHUNK_ (L_ / S_)      // 256
#define MLP_ 8

// Partials, padded row-major: part4[row][s*2 + {0,1}], row = b*C + c.
// Slot layout: {mn0,mn1,mn2,mx0} {mx1,mx2,pad,pad}. 8192 rows * 1KB = 8MB.
__device__ float4 g_part4[(size_t)B_ * C_ * S_ * 2];

__device__ __forceinline__ void ins_min(float v, float& mn0, float& mn1, float& mn2) {
    if (v < mn2) {
        if (v < mn1) {
            mn2 = mn1;
            if (v < mn0) { mn1 = mn0; mn0 = v; }
            else         { mn1 = v; }
        } else {
            mn2 = v;
        }
    }
}

__device__ __forceinline__ void ins_max(float v, float& mx0, float& mx1, float& mx2) {
    if (v > mx2) {
        if (v > mx1) {
            mx2 = mx1;
            if (v > mx0) { mx1 = mx0; mx0 = v; }
            else         { mx1 = v; }
        } else {
            mx2 = v;
        }
    }
}

// Pass 1: grid (S, B) = 1024 blocks x 256 threads = one full resident wave.
// Thread c scans CHUNK_ l-values; quad min/max prefilter so the (rare)
// insert path runs once per 4 elements.
__global__ __launch_bounds__(C_, 8) void kmm_partial(const float* __restrict__ x) {
    const int c = threadIdx.x;
    const int s = blockIdx.x;
    const int b = blockIdx.y;

    const float* __restrict__ p =
        x + ((size_t)b * L_ + (size_t)s * CHUNK_) * C_ + c;

    float mx0 = -CUDART_INF_F, mx1 = -CUDART_INF_F, mx2 = -CUDART_INF_F;
    float mn0 =  CUDART_INF_F, mn1 =  CUDART_INF_F, mn2 =  CUDART_INF_F;

    for (int l = 0; l < CHUNK_; l += MLP_) {
        float v[MLP_];
#pragma unroll
        for (int j = 0; j < MLP_; j++)
            v[j] = __ldg(p + (size_t)(l + j) * C_);
#pragma unroll
        for (int q = 0; q < MLP_; q += 4) {
            float lo = fminf(fminf(v[q], v[q + 1]), fminf(v[q + 2], v[q + 3]));
            float hi = fmaxf(fmaxf(v[q], v[q + 1]), fmaxf(v[q + 2], v[q + 3]));
            if (lo < mn2) {
                ins_min(v[q],     mn0, mn1, mn2);
                ins_min(v[q + 1], mn0, mn1, mn2);
                ins_min(v[q + 2], mn0, mn1, mn2);
                ins_min(v[q + 3], mn0, mn1, mn2);
            }
            if (hi > mx2) {
                ins_max(v[q],     mx0, mx1, mx2);
                ins_max(v[q + 1], mx0, mx1, mx2);
                ins_max(v[q + 2], mx0, mx1, mx2);
                ins_max(v[q + 3], mx0, mx1, mx2);
            }
        }
    }

    float4* o4 = g_part4 + ((size_t)(b * C_ + c) * S_ + s) * 2;
    o4[0] = make_float4(mn0, mn1, mn2, mx0);
    o4[1] = make_float4(mx1, mx2, 0.f, 0.f);
}

// Pass 2: one warp per (b,c) row, lane = s. Each lane: 2x LDG.128, warp reads
// 1KB contiguous (fully coalesced). Butterfly shfl merge of 32 sorted triples.
__global__ __launch_bounds__(256) void kmm_reduce(float* __restrict__ out) {
    const int gtid = blockIdx.x * 256 + threadIdx.x;
    const int row  = gtid >> 5;          // b*C + c
    const int lane = gtid & 31;          // s

    const float4* r4 = g_part4 + ((size_t)row * S_ + lane) * 2;
    float4 a = __ldg(r4);
    float4 bq = __ldg(r4 + 1);

    float mn0 = a.x, mn1 = a.y, mn2 = a.z;
    float mx0 = a.w, mx1 = bq.x, mx2 = bq.y;

#pragma unroll
    for (int off = 16; off > 0; off >>= 1) {
        float b0 = __shfl_xor_sync(0xffffffffu, mn0, off);
        float b1 = __shfl_xor_sync(0xffffffffu, mn1, off);
        float b2 = __shfl_xor_sync(0xffffffffu, mn2, off);
        float c0 = __shfl_xor_sync(0xffffffffu, mx0, off);
        float c1 = __shfl_xor_sync(0xffffffffu, mx1, off);
        float c2 = __shfl_xor_sync(0xffffffffu, mx2, off);

        // merge two ascending min-triples -> 3 smallest of union
        {
            float x0 = fminf(mn0, b0), y0 = fmaxf(mn0, b0);
            float x1 = fminf(mn1, b1);
            float x2 = fminf(mn2, b2);
            mn0 = x0;
            mn1 = fminf(y0, x1);
            mn2 = fminf(x2, fmaxf(x1, y0));
        }
        // merge two descending max-triples -> 3 largest of union
        {
            float x0 = fmaxf(mx0, c0), y0 = fminf(mx0, c0);
            float x1 = fmaxf(mx1, c1);
            float x2 = fmaxf(mx2, c2);
            mx0 = x0;
            mx1 = fmaxf(y0, x1);
            mx2 = fmaxf(x2, fminf(x1, y0));
        }
    }

    if (lane == 0) {
        float* r = out + (size_t)row * 6;
        r[0] = mn0; r[1] = mn1; r[2] = mn2;
        r[3] = mx0; r[4] = mx1; r[5] = mx2;
    }
}

extern "C" void kernel_launch(void* const* d_in, const int* in_sizes, int n_in,
                              void* d_out, int out_size) {
    const float* x = (const float*)d_in[0];
    float* out = (float*)d_out;

    dim3 grid1(S_, B_);
    kmm_partial<<<grid1, C_>>>(x);

    // 8192 rows * 32 lanes = 262144 threads = 1024 blocks x 256
    kmm_reduce<<<(B_ * C_ * 32) / 256, 256>>>(out);
}